// round 16
// baseline (speedup 1.0000x reference)
#include <cuda_runtime.h>
#include <cstdint>

#define SS 200
#define DD 64
#define NOUT 18
#define NT 256
#define CHUNK 100
#define STRIDE 68          // padded floats per embed row (conflict-free, ==4 mod 8)
#define NITER_A 7          // ceil(100/16) row-groups of 16

typedef unsigned long long ull;

// dynamic smem layout (floats):
//   [0, 6800)      s_emb  100 rows x 68 floats  (aliased by scr after last use)
//   [6800, 7600)   s_p    100 x 8               (aliased by s_urep after last use)
//   [7600, 7800)   s_x    200 ints
#define OFF_EMB  0
#define OFF_P    6800
#define OFF_X    7600
#define OFF_SCR  0
#define OFF_UREP 6800
#define DYN_FLOATS 7800

__constant__ __align__(16) float c_attw[5][DD];
__constant__ float c_attb[5];

__device__ float g_loss_part[4096];
__device__ unsigned int g_ticket = 0;

__device__ __forceinline__ ull ffma2(ull a, ull b, ull c) {
    ull d; asm("fma.rn.f32x2 %0, %1, %2, %3;" : "=l"(d) : "l"(a), "l"(b), "l"(c)); return d;
}
__device__ __forceinline__ void unpack2(ull v, float& x, float& y) {
    asm("mov.b64 {%0, %1}, %2;" : "=f"(x), "=f"(y) : "l"(v));
}

// phase-C body: accumulate one row s into (acx, acy, ds)
#define PHASE_C_ROW(s)                                                          \
    do {                                                                        \
        float4 pv = *(const float4*)&dyn[OFF_P + (s) * 8];                      \
        float  p4 = dyn[OFF_P + (s) * 8 + 4];                                   \
        float2 e  = *(const float2*)&dyn[OFF_EMB + (s) * STRIDE + lane * 2];    \
        acx[0] = fmaf(pv.x, e.x, acx[0]); acy[0] = fmaf(pv.x, e.y, acy[0]);     \
        acx[1] = fmaf(pv.y, e.x, acx[1]); acy[1] = fmaf(pv.y, e.y, acy[1]);     \
        acx[2] = fmaf(pv.z, e.x, acx[2]); acy[2] = fmaf(pv.z, e.y, acy[2]);     \
        acx[3] = fmaf(pv.w, e.x, acx[3]); acy[3] = fmaf(pv.w, e.y, acy[3]);     \
        acx[4] = fmaf(p4,   e.x, acx[4]); acy[4] = fmaf(p4,   e.y, acy[4]);     \
        ds[0] += pv.x; ds[1] += pv.y; ds[2] += pv.z; ds[3] += pv.w; ds[4] += p4;\
    } while (0)

__global__ __launch_bounds__(NT, 7) void tan_kernel(
    const int* __restrict__ x, const float* __restrict__ y,
    const float* __restrict__ emb,
    const float* __restrict__ W0, const float* __restrict__ W1,
    const float* __restrict__ W2, const float* __restrict__ W3,
    const float* __restrict__ W4,
    float* __restrict__ out, int out_size)
{
    extern __shared__ float dyn[];
    __shared__ float s_dcomb[8 * 5];
    __shared__ float s_deninv[5];
    __shared__ float s_wu[NOUT];
    __shared__ float s_lossi[5];
    __shared__ int   s_last;

    const int b    = blockIdx.x;
    const int t    = threadIdx.x;
    const int lane = t & 31;
    const int warp = t >> 5;
    const int q    = t & 15;      // 16B-chunk index within a row (phase A)
    const int slot = t >> 4;      // row-within-group (phase A)

    int* s_x = (int*)&dyn[OFF_X];
    float* s_urep = &dyn[OFF_UREP];

    const uint32_t sbase = (uint32_t)__cvta_generic_to_shared(dyn);
    const uint32_t a_emb = sbase + OFF_EMB * 4;

    // ---- stage x row ----
    for (int i = t; i < SS; i += NT) s_x[i] = x[b * SS + i];
    __syncthreads();

    // scalar accumulators: lane = d-pair (acx = even d, acy = odd d); persist across chunks
    float acx[5], acy[5], ds[5];
#pragma unroll
    for (int k = 0; k < 5; ++k) { acx[k] = 0.f; acy[k] = 0.f; ds[k] = 0.f; }

    for (int ch = 0; ch < 2; ++ch) {
        // ===== Phase A: coalesced gather via cp.async (no register staging) =====
#pragma unroll
        for (int i = 0; i < NITER_A; ++i) {
            int row = i * 16 + slot;
            if (row < CHUNK) {
                const float* gp = &emb[(size_t)s_x[ch * CHUNK + row] * DD + q * 4];
                uint32_t dst = a_emb + (uint32_t)(row * STRIDE + q * 4) * 4;
                asm volatile("cp.async.cg.shared.global [%0], [%1], 16;"
                             :: "r"(dst), "l"(gp));
            }
        }
        asm volatile("cp.async.commit_group;");
        asm volatile("cp.async.wait_group 0;");
        __syncthreads();

        // ===== Phase B: scores (thread = row); 64-bit constant loads =====
        if (t < CHUNK) {
            ull su[5];
#pragma unroll
            for (int k = 0; k < 5; ++k) su[k] = 0ull;
            const uint32_t rbase = a_emb + (uint32_t)(t * STRIDE) * 4;
#pragma unroll 4
            for (int c = 0; c < 16; ++c) {
                ull g01, g23;
                asm("ld.shared.v2.u64 {%0, %1}, [%2];"
                    : "=l"(g01), "=l"(g23) : "r"(rbase + (uint32_t)(c * 16)));
#pragma unroll
                for (int k = 0; k < 5; ++k) {
                    ull w01 = *(const ull*)&c_attw[k][c * 4];
                    ull w23 = *(const ull*)&c_attw[k][c * 4 + 2];
                    su[k] = ffma2(g01, w01, su[k]);
                    su[k] = ffma2(g23, w23, su[k]);
                }
            }
            float p[5];
#pragma unroll
            for (int k = 0; k < 5; ++k) {
                float lo, hi;
                unpack2(su[k], lo, hi);
                float u = lo + hi + c_attb[k];
                p[k] = __expf(__tanhf(u));     // |tanh|<=1, no max-sub needed
            }
            *(float4*)&dyn[OFF_P + t * 8] = make_float4(p[0], p[1], p[2], p[3]);
            dyn[OFF_P + t * 8 + 4] = p[4];
        }
        __syncthreads();

        // ===== Phase C: fully unrolled (12 static + 1 guarded tail) =====
        {
#pragma unroll
            for (int i = 0; i < 12; ++i) {
                const int s = warp + i * 8;        // compile-time offset per i
                PHASE_C_ROW(s);
            }
            if (warp < 4) {                         // rows 96..99
                const int s = warp + 96;
                PHASE_C_ROW(s);
            }
        }
        __syncthreads();   // emb reads done: chunk 0 -> refill; chunk 1 -> scr alias safe
    }

    // ---- per-warp partials into scratch (aliases emb tile) ----
#pragma unroll
    for (int k = 0; k < 5; ++k) {
        *(float2*)&dyn[OFF_SCR + ((warp * 5 + k) * 32 + lane) * 2] =
            make_float2(acx[k], acy[k]);
    }
    if (lane == 0) {
#pragma unroll
        for (int k = 0; k < 5; ++k) s_dcomb[warp * 5 + k] = ds[k];
    }
    __syncthreads();

    if (t < 5) {
        float dn = 0.f;
#pragma unroll
        for (int w = 0; w < 8; ++w) dn += s_dcomb[w * 5 + t];
        s_deninv[t] = 1.0f / dn;
    }
    if (t < 160) {
        int k = t >> 5, d2 = t & 31;
        float sx = 0.f, sy = 0.f;
#pragma unroll
        for (int w = 0; w < 8; ++w) {
            float2 v = *(const float2*)&dyn[OFF_SCR + ((w * 5 + k) * 32 + d2) * 2];
            sx += v.x; sy += v.y;
        }
        s_urep[k * DD + d2 * 2]     = sx;   // aliases dead s_p region
        s_urep[k * DD + d2 * 2 + 1] = sy;
    }
    __syncthreads();

    // ===== Phase 5: W_user = user_rep @ Wi^T =====
    for (int j = warp; j < NOUT; j += 8) {
        int i = (j < 2) ? 0 : (j < 6) ? 1 : (j < 10) ? 2 : (j < 12) ? 3 : 4;
        int bse = (i == 0) ? 0 : (i == 1) ? 2 : (i == 2) ? 6 : (i == 3) ? 10 : 12;
        int r = j - bse;
        const float* w = (i == 0) ? W0 : (i == 1) ? W1 : (i == 2) ? W2 : (i == 3) ? W3 : W4;
        float v = s_urep[i * DD + lane]      * __ldg(&w[r * DD + lane])
                + s_urep[i * DD + 32 + lane] * __ldg(&w[r * DD + 32 + lane]);
#pragma unroll
        for (int m = 16; m >= 1; m >>= 1) v += __shfl_xor_sync(0xffffffffu, v, m);
        if (lane == 0) s_wu[j] = v * s_deninv[i];
    }
    __syncthreads();

    // ===== Phase 6: group softmax + CE =====
    if (t < 5) {
        int c0 = (t == 0) ? 0 : (t == 1) ? 2 : (t == 2) ? 6 : (t == 3) ? 10 : 12;
        int n  = (t == 0) ? 2 : (t == 1) ? 4 : (t == 2) ? 4 : (t == 3) ? 2 : 6;
        float m = -1e30f;
#pragma unroll 6
        for (int j = 0; j < 6; ++j) if (j < n) m = fmaxf(m, s_wu[c0 + j]);
        float ex[6], sum = 0.f;
#pragma unroll 6
        for (int j = 0; j < 6; ++j) {
            ex[j] = (j < n) ? __expf(s_wu[c0 + j] - m) : 0.f;
            sum += ex[j];
        }
        float inv = 1.0f / sum;
        float lse = __logf(sum);
        float li = 0.f;
#pragma unroll 6
        for (int j = 0; j < 6; ++j) {
            if (j < n) {
                out[b * NOUT + c0 + j] = ex[j] * inv;
                float logp = s_wu[c0 + j] - m - lse;
                li -= logp * __ldg(&y[b * NOUT + c0 + j]);
            }
        }
        s_lossi[t] = li;
    }
    __syncthreads();

    // ===== fused deterministic loss reduction (last block) =====
    if (t == 0) {
        float loss = s_lossi[0] + s_lossi[1] + s_lossi[2] + s_lossi[3] + s_lossi[4];
        __stcg(&g_loss_part[b], loss);
        __threadfence();
        unsigned old = atomicAdd(&g_ticket, 1u);
        s_last = (old == gridDim.x - 1) ? 1 : 0;
    }
    __syncthreads();
    if (s_last) {
        int B = gridDim.x;
        float v = 0.f;
        for (int i = t; i < B; i += NT) v += __ldcg(&g_loss_part[i]);
#pragma unroll
        for (int m = 16; m >= 1; m >>= 1) v += __shfl_xor_sync(0xffffffffu, v, m);
        if (lane == 0) s_dcomb[warp] = v;
        __syncthreads();
        if (t == 0) {
            float s = 0.f;
#pragma unroll
            for (int w = 0; w < 8; ++w) s += s_dcomb[w];
            out[out_size - 1] = s / (float)B;
            g_ticket = 0;   // reset for next graph replay
        }
    }
}

extern "C" void kernel_launch(void* const* d_in, const int* in_sizes, int n_in,
                              void* d_out, int out_size)
{
    const int*   x    = (const int*)d_in[0];
    const float* y    = (const float*)d_in[1];
    const float* emb  = (const float*)d_in[2];
    const float* attw = (const float*)d_in[3];
    const float* attb = (const float*)d_in[4];
    const float* W0   = (const float*)d_in[5];
    const float* W1   = (const float*)d_in[6];
    const float* W2   = (const float*)d_in[7];
    const float* W3   = (const float*)d_in[8];
    const float* W4   = (const float*)d_in[9];
    float* out = (float*)d_out;

    int B = in_sizes[0] / SS;   // 4096
    size_t dyn_bytes = (size_t)DYN_FLOATS * sizeof(float);   // 31200

    static int attr_set = 0;
    if (!attr_set) {
        cudaFuncSetAttribute(tan_kernel,
                             cudaFuncAttributeMaxDynamicSharedMemorySize,
                             (int)dyn_bytes);
        attr_set = 1;
    }

    // Stage attention weights/bias into __constant__ (D2D async: graph-capturable)
    cudaMemcpyToSymbolAsync(c_attw, attw, 5 * DD * sizeof(float), 0,
                            cudaMemcpyDeviceToDevice, 0);
    cudaMemcpyToSymbolAsync(c_attb, attb, 5 * sizeof(float), 0,
                            cudaMemcpyDeviceToDevice, 0);

    tan_kernel<<<B, NT, dyn_bytes>>>(x, y, emb,
                                     W0, W1, W2, W3, W4, out, out_size);
}

// round 17
// speedup vs baseline: 1.1763x; 1.1763x over previous
#include <cuda_runtime.h>
#include <cstdint>

#define SS 200
#define DD 64
#define NOUT 18
#define NT 256
#define CHUNK 100
#define STRIDE 68          // padded floats per embed row (conflict-free, ==4 mod 8)
#define NITER_A 7          // ceil(100/16) row-groups of 16

typedef unsigned long long ull;

// dynamic smem layout (floats):
//   [0, 6800)      s_emb  100 rows x 68 floats  (aliased by scr after last use)
//   [6800, 7600)   s_p    100 x 8               (aliased by s_urep after last use)
//   [7600, 7800)   s_x    200 ints
#define OFF_EMB  0
#define OFF_P    6800
#define OFF_X    7600
#define OFF_SCR  0
#define OFF_UREP 6800
#define DYN_FLOATS 7800

__constant__ __align__(16) float c_attw[5][DD];
__constant__ float c_attb[5];

__device__ float g_loss_part[4096];
__device__ unsigned int g_ticket = 0;

__device__ __forceinline__ ull ffma2(ull a, ull b, ull c) {
    ull d; asm("fma.rn.f32x2 %0, %1, %2, %3;" : "=l"(d) : "l"(a), "l"(b), "l"(c)); return d;
}
__device__ __forceinline__ void unpack2(ull v, float& x, float& y) {
    asm("mov.b64 {%0, %1}, %2;" : "=f"(x), "=f"(y) : "l"(v));
}

__global__ __launch_bounds__(NT, 7) void tan_kernel(
    const int* __restrict__ x, const float* __restrict__ y,
    const float* __restrict__ emb,
    const float* __restrict__ W0, const float* __restrict__ W1,
    const float* __restrict__ W2, const float* __restrict__ W3,
    const float* __restrict__ W4,
    float* __restrict__ out, int out_size)
{
    extern __shared__ float dyn[];
    __shared__ float s_bsum[4 * 5];     // per-B-warp denominator partials (accum over chunks)
    __shared__ float s_deninv[5];
    __shared__ float s_wu[NOUT];
    __shared__ float s_lossi[5];
    __shared__ float s_lred[8];
    __shared__ int   s_last;

    const int b    = blockIdx.x;
    const int t    = threadIdx.x;
    const int lane = t & 31;
    const int warp = t >> 5;
    const int q    = t & 15;      // 16B-chunk index within a row (phase A)
    const int slot = t >> 4;      // row-within-group (phase A)

    int* s_x = (int*)&dyn[OFF_X];
    float* s_urep = &dyn[OFF_UREP];

    const uint32_t sbase = (uint32_t)__cvta_generic_to_shared(dyn);
    const uint32_t a_emb = sbase + OFF_EMB * 4;

    // ---- stage x row ----
    for (int i = t; i < SS; i += NT) s_x[i] = x[b * SS + i];
    __syncthreads();

    // scalar accumulators: lane = d-pair (acx = even d, acy = odd d); persist across chunks
    float acx[5], acy[5];
#pragma unroll
    for (int k = 0; k < 5; ++k) { acx[k] = 0.f; acy[k] = 0.f; }

    for (int ch = 0; ch < 2; ++ch) {
        // ===== Phase A: coalesced gather via cp.async (no register staging) =====
#pragma unroll
        for (int i = 0; i < NITER_A; ++i) {
            int row = i * 16 + slot;
            if (row < CHUNK) {
                const float* gp = &emb[(size_t)s_x[ch * CHUNK + row] * DD + q * 4];
                uint32_t dst = a_emb + (uint32_t)(row * STRIDE + q * 4) * 4;
                asm volatile("cp.async.cg.shared.global [%0], [%1], 16;"
                             :: "r"(dst), "l"(gp));
            }
        }
        asm volatile("cp.async.commit_group;");
        asm volatile("cp.async.wait_group 0;");
        __syncthreads();

        // ===== Phase B: scores (warps 0-3; thread = row) + denominator reduce =====
        if (t < 128) {
            float p[5];
            if (t < CHUNK) {
                ull su[5];
#pragma unroll
                for (int k = 0; k < 5; ++k) su[k] = 0ull;
                const uint32_t rbase = a_emb + (uint32_t)(t * STRIDE) * 4;
#pragma unroll 4
                for (int c = 0; c < 16; ++c) {
                    ull g01, g23;
                    asm("ld.shared.v2.u64 {%0, %1}, [%2];"
                        : "=l"(g01), "=l"(g23) : "r"(rbase + (uint32_t)(c * 16)));
#pragma unroll
                    for (int k = 0; k < 5; ++k) {
                        ull w01 = *(const ull*)&c_attw[k][c * 4];
                        ull w23 = *(const ull*)&c_attw[k][c * 4 + 2];
                        su[k] = ffma2(g01, w01, su[k]);
                        su[k] = ffma2(g23, w23, su[k]);
                    }
                }
#pragma unroll
                for (int k = 0; k < 5; ++k) {
                    float lo, hi;
                    unpack2(su[k], lo, hi);
                    float u = lo + hi + c_attb[k];
                    p[k] = __expf(__tanhf(u));   // |tanh|<=1, no max-sub needed
                }
                *(float4*)&dyn[OFF_P + t * 8] = make_float4(p[0], p[1], p[2], p[3]);
                dyn[OFF_P + t * 8 + 4] = p[4];
            } else {
#pragma unroll
                for (int k = 0; k < 5; ++k) p[k] = 0.f;   // tail lanes: identity for sum
            }
            // warp-reduce denominator partials (full warps: t<128)
#pragma unroll
            for (int m = 16; m >= 1; m >>= 1) {
#pragma unroll
                for (int k = 0; k < 5; ++k)
                    p[k] += __shfl_xor_sync(0xffffffffu, p[k], m);
            }
            if (lane == 0) {
#pragma unroll
                for (int k = 0; k < 5; ++k) {
                    if (ch == 0) s_bsum[warp * 5 + k] = p[k];
                    else         s_bsum[warp * 5 + k] += p[k];
                }
            }
        }
        __syncthreads();

        // ===== Phase C: accumulate numerators (scalar FMA; no denominator work) =====
        for (int s = warp; s < CHUNK; s += 8) {
            float4 pv = *(const float4*)&dyn[OFF_P + s * 8];
            float  p4 = dyn[OFF_P + s * 8 + 4];
            float2 e  = *(const float2*)&dyn[OFF_EMB + s * STRIDE + lane * 2];
            acx[0] = fmaf(pv.x, e.x, acx[0]); acy[0] = fmaf(pv.x, e.y, acy[0]);
            acx[1] = fmaf(pv.y, e.x, acx[1]); acy[1] = fmaf(pv.y, e.y, acy[1]);
            acx[2] = fmaf(pv.z, e.x, acx[2]); acy[2] = fmaf(pv.z, e.y, acy[2]);
            acx[3] = fmaf(pv.w, e.x, acx[3]); acy[3] = fmaf(pv.w, e.y, acy[3]);
            acx[4] = fmaf(p4,   e.x, acx[4]); acy[4] = fmaf(p4,   e.y, acy[4]);
        }
        __syncthreads();   // emb reads done: chunk 0 -> refill; chunk 1 -> scr alias safe
    }

    // ---- per-warp partials into scratch (aliases emb tile) ----
#pragma unroll
    for (int k = 0; k < 5; ++k) {
        *(float2*)&dyn[OFF_SCR + ((warp * 5 + k) * 32 + lane) * 2] =
            make_float2(acx[k], acy[k]);
    }
    __syncthreads();

    if (t < 5) {
        float dn = s_bsum[t] + s_bsum[5 + t] + s_bsum[10 + t] + s_bsum[15 + t];
        s_deninv[t] = 1.0f / dn;
    }
    if (t < 160) {
        int k = t >> 5, d2 = t & 31;
        float sx = 0.f, sy = 0.f;
#pragma unroll
        for (int w = 0; w < 8; ++w) {
            float2 v = *(const float2*)&dyn[OFF_SCR + ((w * 5 + k) * 32 + d2) * 2];
            sx += v.x; sy += v.y;
        }
        s_urep[k * DD + d2 * 2]     = sx;   // aliases dead s_p region
        s_urep[k * DD + d2 * 2 + 1] = sy;
    }
    __syncthreads();

    // ===== Phase 5: W_user = user_rep @ Wi^T =====
    for (int j = warp; j < NOUT; j += 8) {
        int i = (j < 2) ? 0 : (j < 6) ? 1 : (j < 10) ? 2 : (j < 12) ? 3 : 4;
        int bse = (i == 0) ? 0 : (i == 1) ? 2 : (i == 2) ? 6 : (i == 3) ? 10 : 12;
        int r = j - bse;
        const float* w = (i == 0) ? W0 : (i == 1) ? W1 : (i == 2) ? W2 : (i == 3) ? W3 : W4;
        float v = s_urep[i * DD + lane]      * __ldg(&w[r * DD + lane])
                + s_urep[i * DD + 32 + lane] * __ldg(&w[r * DD + 32 + lane]);
#pragma unroll
        for (int m = 16; m >= 1; m >>= 1) v += __shfl_xor_sync(0xffffffffu, v, m);
        if (lane == 0) s_wu[j] = v * s_deninv[i];
    }
    __syncthreads();

    // ===== Phase 6: group softmax + CE =====
    if (t < 5) {
        int c0 = (t == 0) ? 0 : (t == 1) ? 2 : (t == 2) ? 6 : (t == 3) ? 10 : 12;
        int n  = (t == 0) ? 2 : (t == 1) ? 4 : (t == 2) ? 4 : (t == 3) ? 2 : 6;
        float m = -1e30f;
#pragma unroll 6
        for (int j = 0; j < 6; ++j) if (j < n) m = fmaxf(m, s_wu[c0 + j]);
        float ex[6], sum = 0.f;
#pragma unroll 6
        for (int j = 0; j < 6; ++j) {
            ex[j] = (j < n) ? __expf(s_wu[c0 + j] - m) : 0.f;
            sum += ex[j];
        }
        float inv = 1.0f / sum;
        float lse = __logf(sum);
        float li = 0.f;
#pragma unroll 6
        for (int j = 0; j < 6; ++j) {
            if (j < n) {
                out[b * NOUT + c0 + j] = ex[j] * inv;
                float logp = s_wu[c0 + j] - m - lse;
                li -= logp * __ldg(&y[b * NOUT + c0 + j]);
            }
        }
        s_lossi[t] = li;
    }
    __syncthreads();

    // ===== fused deterministic loss reduction (last block) =====
    if (t == 0) {
        float loss = s_lossi[0] + s_lossi[1] + s_lossi[2] + s_lossi[3] + s_lossi[4];
        __stcg(&g_loss_part[b], loss);
        __threadfence();
        unsigned old = atomicAdd(&g_ticket, 1u);
        s_last = (old == gridDim.x - 1) ? 1 : 0;
    }
    __syncthreads();
    if (s_last) {
        int B = gridDim.x;
        float v = 0.f;
        for (int i = t; i < B; i += NT) v += __ldcg(&g_loss_part[i]);
#pragma unroll
        for (int m = 16; m >= 1; m >>= 1) v += __shfl_xor_sync(0xffffffffu, v, m);
        if (lane == 0) s_lred[warp] = v;
        __syncthreads();
        if (t == 0) {
            float s = 0.f;
#pragma unroll
            for (int w = 0; w < 8; ++w) s += s_lred[w];
            out[out_size - 1] = s / (float)B;
            g_ticket = 0;   // reset for next graph replay
        }
    }
}

extern "C" void kernel_launch(void* const* d_in, const int* in_sizes, int n_in,
                              void* d_out, int out_size)
{
    const int*   x    = (const int*)d_in[0];
    const float* y    = (const float*)d_in[1];
    const float* emb  = (const float*)d_in[2];
    const float* attw = (const float*)d_in[3];
    const float* attb = (const float*)d_in[4];
    const float* W0   = (const float*)d_in[5];
    const float* W1   = (const float*)d_in[6];
    const float* W2   = (const float*)d_in[7];
    const float* W3   = (const float*)d_in[8];
    const float* W4   = (const float*)d_in[9];
    float* out = (float*)d_out;

    int B = in_sizes[0] / SS;   // 4096
    size_t dyn_bytes = (size_t)DYN_FLOATS * sizeof(float);   // 31200

    static int attr_set = 0;
    if (!attr_set) {
        cudaFuncSetAttribute(tan_kernel,
                             cudaFuncAttributeMaxDynamicSharedMemorySize,
                             (int)dyn_bytes);
        attr_set = 1;
    }

    // Stage attention weights/bias into __constant__ (D2D async: graph-capturable)
    cudaMemcpyToSymbolAsync(c_attw, attw, 5 * DD * sizeof(float), 0,
                            cudaMemcpyDeviceToDevice, 0);
    cudaMemcpyToSymbolAsync(c_attb, attb, 5 * sizeof(float), 0,
                            cudaMemcpyDeviceToDevice, 0);

    tan_kernel<<<B, NT, dyn_bytes>>>(x, y, emb,
                                     W0, W1, W2, W3, W4, out, out_size);
}